// round 1
// baseline (speedup 1.0000x reference)
#include <cuda_runtime.h>
#include <math.h>

// Problem constants (fixed by the dataset instance)
constexpr int DM = 1024;   // d_model
constexpr int H  = 16;     // heads
constexpr int DH = 64;     // head dim
constexpr int B  = 4;      // batch
constexpr int S  = 2048;   // seq len
constexpr int M  = B * S;  // 8192 rows

// Scratch (allocation-free rule: __device__ globals)
__device__ float g_q[(size_t)B * H * S * DH];
__device__ float g_k[(size_t)B * H * S * DH];
__device__ float g_v[(size_t)B * H * S * DH];
__device__ float g_ao[(size_t)B * S * DM];

// ---------------------------------------------------------------------------
// GEMM: C = A[M,K] @ W[N,K]^T  (both row-major, K contiguous -> NT gemm)
// 128x128 block tile, BK=16, 256 threads, 8x8 microtile (split 4+4 scheme).
// PERM=1 writes output permuted into [b,h,s,d] head-major layout.
// ---------------------------------------------------------------------------
template <int PERM>
__global__ __launch_bounds__(256) void gemm_nt(const float* __restrict__ A,
                                               const float* __restrict__ W,
                                               float* __restrict__ C,
                                               int Mdim, int Ndim, int Kdim) {
    __shared__ __align__(16) float ash[16][132];
    __shared__ __align__(16) float bsh[16][132];

    const int tid = threadIdx.x;
    const int tx = tid & 15;        // 0..15 -> N microtiles
    const int ty = tid >> 4;        // 0..15 -> M microtiles
    const int bm = blockIdx.y;
    const int bn = blockIdx.x;

    const float4* A4 = (const float4*)A;
    const float4* W4 = (const float4*)W;
    const int K4 = Kdim >> 2;

    float acc[8][8];
#pragma unroll
    for (int i = 0; i < 8; i++)
#pragma unroll
        for (int j = 0; j < 8; j++) acc[i][j] = 0.f;

    for (int k0 = 0; k0 < Kdim; k0 += 16) {
        // Load 128x16 tiles of A and W, transposed into smem [k][row]
#pragma unroll
        for (int it = 0; it < 2; it++) {
            int id = tid + it * 256;        // 0..511
            int r  = id >> 2;               // 0..127
            int c4 = id & 3;                // 0..3 (float4 within the 16 k's)
            float4 va = A4[(size_t)(bm * 128 + r) * K4 + (k0 >> 2) + c4];
            ash[c4 * 4 + 0][r] = va.x;
            ash[c4 * 4 + 1][r] = va.y;
            ash[c4 * 4 + 2][r] = va.z;
            ash[c4 * 4 + 3][r] = va.w;
            float4 vb = W4[(size_t)(bn * 128 + r) * K4 + (k0 >> 2) + c4];
            bsh[c4 * 4 + 0][r] = vb.x;
            bsh[c4 * 4 + 1][r] = vb.y;
            bsh[c4 * 4 + 2][r] = vb.z;
            bsh[c4 * 4 + 3][r] = vb.w;
        }
        __syncthreads();

#pragma unroll
        for (int kk = 0; kk < 16; kk++) {
            float a[8], b[8];
            *(float4*)&a[0] = *(const float4*)&ash[kk][ty * 4];
            *(float4*)&a[4] = *(const float4*)&ash[kk][64 + ty * 4];
            *(float4*)&b[0] = *(const float4*)&bsh[kk][tx * 4];
            *(float4*)&b[4] = *(const float4*)&bsh[kk][64 + tx * 4];
#pragma unroll
            for (int i = 0; i < 8; i++)
#pragma unroll
                for (int j = 0; j < 8; j++) acc[i][j] += a[i] * b[j];
        }
        __syncthreads();
    }

    // Writeback
#pragma unroll
    for (int i = 0; i < 8; i++) {
        int mrow = bm * 128 + ((i < 4) ? (ty * 4 + i) : (64 + ty * 4 + i - 4));
#pragma unroll
        for (int j = 0; j < 8; j++) {
            int ncol = bn * 128 + ((j < 4) ? (tx * 4 + j) : (64 + tx * 4 + j - 4));
            if (PERM == 0) {
                C[(size_t)mrow * Ndim + ncol] = acc[i][j];
            } else {
                // [b,s] x [h,d] -> [b,h,s,d]
                int b_ = mrow >> 11;       // / S
                int s_ = mrow & 2047;      // % S
                int h_ = ncol >> 6;        // / DH
                int d_ = ncol & 63;        // % DH
                C[((((size_t)b_ * H + h_) * S + s_) << 6) + d_] = acc[i][j];
            }
        }
    }
}

// ---------------------------------------------------------------------------
// Causal flash attention, fp32. One thread owns one query row (q+acc in regs).
// Block: 128 threads = 128 query rows. K/V tiles of 64 keys in smem
// (reads are warp-broadcast -> conflict-free).
// Output written as [b, s, h*64+d] so the final O-projection is a plain GEMM.
// ---------------------------------------------------------------------------
__global__ __launch_bounds__(128) void attn_kernel(const float* __restrict__ Q,
                                                   const float* __restrict__ K,
                                                   const float* __restrict__ V,
                                                   float* __restrict__ O) {
    __shared__ __align__(16) float ksh[64][64];
    __shared__ __align__(16) float vsh[64][64];

    const int tid = threadIdx.x;
    const int qt = blockIdx.x;
    const int h  = blockIdx.y;
    const int b  = blockIdx.z;
    const int qi = qt * 128 + tid;

    const size_t headoff = (((size_t)b * H + h) * S) * DH;
    const float* qbase = Q + headoff;
    const float* kbase = K + headoff;
    const float* vbase = V + headoff;

    // Load this thread's query row into registers
    float q[64];
    {
        const float4* q4 = (const float4*)(qbase + (size_t)qi * DH);
#pragma unroll
        for (int d4 = 0; d4 < 16; d4++) {
            float4 t = q4[d4];
            q[d4 * 4 + 0] = t.x; q[d4 * 4 + 1] = t.y;
            q[d4 * 4 + 2] = t.z; q[d4 * 4 + 3] = t.w;
        }
    }

    float acc[64];
#pragma unroll
    for (int d = 0; d < 64; d++) acc[d] = 0.f;
    float mval = -1e30f;
    float lsum = 0.f;

    const int nkt = (qt * 128 + 128) / 64;  // tiles covering causal span of block

    for (int kt = 0; kt < nkt; kt++) {
        // Cooperative tile load (coalesced float4)
        const float4* ksrc = (const float4*)(kbase + (size_t)kt * 64 * DH);
        const float4* vsrc = (const float4*)(vbase + (size_t)kt * 64 * DH);
        float4* kdst = (float4*)&ksh[0][0];
        float4* vdst = (float4*)&vsh[0][0];
#pragma unroll
        for (int i = 0; i < 8; i++) {
            kdst[tid + i * 128] = ksrc[tid + i * 128];
            vdst[tid + i * 128] = vsrc[tid + i * 128];
        }
        __syncthreads();

        int rel = qi - kt * 64;                         // last valid j (inclusive)
        int jend = rel >= 63 ? 64 : (rel + 1);
        if (jend < 0) jend = 0;

        for (int j = 0; j < jend; j++) {
            const float4* kr = (const float4*)&ksh[j][0];
            float s = 0.f;
#pragma unroll
            for (int d4 = 0; d4 < 16; d4++) {
                float4 kv = kr[d4];
                s += q[d4 * 4 + 0] * kv.x + q[d4 * 4 + 1] * kv.y +
                     q[d4 * 4 + 2] * kv.z + q[d4 * 4 + 3] * kv.w;
            }
            s *= 0.125f;  // 1/sqrt(64)

            const float4* vr = (const float4*)&vsh[j][0];
            if (s <= mval) {
                float p = __expf(s - mval);
                lsum += p;
#pragma unroll
                for (int d4 = 0; d4 < 16; d4++) {
                    float4 vv = vr[d4];
                    acc[d4 * 4 + 0] += p * vv.x;
                    acc[d4 * 4 + 1] += p * vv.y;
                    acc[d4 * 4 + 2] += p * vv.z;
                    acc[d4 * 4 + 3] += p * vv.w;
                }
            } else {
                float sc = __expf(mval - s);
                mval = s;
                lsum = lsum * sc + 1.f;
#pragma unroll
                for (int d4 = 0; d4 < 16; d4++) {
                    float4 vv = vr[d4];
                    acc[d4 * 4 + 0] = acc[d4 * 4 + 0] * sc + vv.x;
                    acc[d4 * 4 + 1] = acc[d4 * 4 + 1] * sc + vv.y;
                    acc[d4 * 4 + 2] = acc[d4 * 4 + 2] * sc + vv.z;
                    acc[d4 * 4 + 3] = acc[d4 * 4 + 3] * sc + vv.w;
                }
            }
        }
        __syncthreads();
    }

    const float inv = 1.f / lsum;
    float4* o4 = (float4*)(O + ((size_t)b * S + qi) * DM + h * DH);
#pragma unroll
    for (int d4 = 0; d4 < 16; d4++) {
        o4[d4] = make_float4(acc[d4 * 4 + 0] * inv, acc[d4 * 4 + 1] * inv,
                             acc[d4 * 4 + 2] * inv, acc[d4 * 4 + 3] * inv);
    }
}

// ---------------------------------------------------------------------------
extern "C" void kernel_launch(void* const* d_in, const int* in_sizes, int n_in,
                              void* d_out, int out_size) {
    // Inputs (dict order): num_heads (1), wq, wk, wv, wo (1024*1024 each),
    // in_features (B*S*DM). Identify robustly by size.
    const float* w[4] = {nullptr, nullptr, nullptr, nullptr};
    const float* x = nullptr;
    int wn = 0;
    for (int i = 0; i < n_in; i++) {
        if (in_sizes[i] == DM * DM && wn < 4) {
            w[wn++] = (const float*)d_in[i];
        } else if (in_sizes[i] == B * S * DM) {
            x = (const float*)d_in[i];
        }
    }

    float *q, *k, *v, *ao;
    cudaGetSymbolAddress((void**)&q, g_q);
    cudaGetSymbolAddress((void**)&k, g_k);
    cudaGetSymbolAddress((void**)&v, g_v);
    cudaGetSymbolAddress((void**)&ao, g_ao);

    dim3 ggrid(DM / 128, M / 128);  // (8, 64)
    gemm_nt<1><<<ggrid, 256>>>(x, w[0], q, M, DM, DM);
    gemm_nt<1><<<ggrid, 256>>>(x, w[1], k, M, DM, DM);
    gemm_nt<1><<<ggrid, 256>>>(x, w[2], v, M, DM, DM);

    dim3 agrid(S / 128, H, B);      // (16, 16, 4)
    attn_kernel<<<agrid, 128>>>(q, k, v, ao);

    gemm_nt<0><<<ggrid, 256>>>(ao, w[3], (float*)d_out, M, DM, DM);
}

// round 3
// speedup vs baseline: 1.3271x; 1.3271x over previous
#include <cuda_runtime.h>
#include <cuda_bf16.h>
#include <cstdint>
#include <math.h>

// Problem constants
constexpr int DM = 1024;   // d_model
constexpr int H  = 16;     // heads
constexpr int DH = 64;     // head dim
constexpr int B  = 4;      // batch
constexpr int S  = 2048;   // seq len
constexpr int M  = B * S;  // 8192 rows

// Scratch (allocation-free rule: __device__ globals)
__device__ float g_q[(size_t)B * H * S * DH];
__device__ float g_k[(size_t)B * H * S * DH];
__device__ float g_v[(size_t)B * H * S * DH];
__device__ float g_ao[(size_t)B * S * DM];
__device__ __nv_bfloat16 g_xhi[(size_t)M * DM];
__device__ __nv_bfloat16 g_xlo[(size_t)M * DM];
__device__ __nv_bfloat16 g_whi[(size_t)4 * DM * DM];
__device__ __nv_bfloat16 g_wlo[(size_t)4 * DM * DM];
__device__ __nv_bfloat16 g_aohi[(size_t)M * DM];
__device__ __nv_bfloat16 g_aolo[(size_t)M * DM];

// ---------------------------------------------------------------------------
// PTX helpers (compute_103-safe: mma.sync / ldmatrix / cp.async only)
// ---------------------------------------------------------------------------
__device__ __forceinline__ uint32_t smem_u32(const void* p) {
    uint32_t a;
    asm("{ .reg .u64 t; cvta.to.shared.u64 t, %1; cvt.u32.u64 %0, t; }"
        : "=r"(a) : "l"(p));
    return a;
}
__device__ __forceinline__ void cp16(uint32_t saddr, const void* gaddr) {
    asm volatile("cp.async.cg.shared.global [%0], [%1], 16;"
                 :: "r"(saddr), "l"(gaddr) : "memory");
}
__device__ __forceinline__ void cp_commit() {
    asm volatile("cp.async.commit_group;" ::: "memory");
}
__device__ __forceinline__ void cp_wait1() {
    asm volatile("cp.async.wait_group 1;" ::: "memory");
}
__device__ __forceinline__ void ldsm4(uint32_t* r, uint32_t addr) {
    asm volatile("ldmatrix.sync.aligned.m8n8.x4.shared.b16 {%0,%1,%2,%3}, [%4];"
                 : "=r"(r[0]), "=r"(r[1]), "=r"(r[2]), "=r"(r[3]) : "r"(addr));
}
__device__ __forceinline__ void mma16816(float* c, const uint32_t* a, const uint32_t* b) {
    asm volatile(
        "mma.sync.aligned.m16n8k16.row.col.f32.bf16.bf16.f32 "
        "{%0,%1,%2,%3}, {%4,%5,%6,%7}, {%8,%9}, {%0,%1,%2,%3};"
        : "+f"(c[0]), "+f"(c[1]), "+f"(c[2]), "+f"(c[3])
        : "r"(a[0]), "r"(a[1]), "r"(a[2]), "r"(a[3]), "r"(b[0]), "r"(b[1]));
}

// ---------------------------------------------------------------------------
// fp32 -> (bf16 hi, bf16 lo) split, vectorized
// ---------------------------------------------------------------------------
__global__ __launch_bounds__(256) void split_bf16(const float4* __restrict__ src,
                                                  __nv_bfloat162* __restrict__ hi,
                                                  __nv_bfloat162* __restrict__ lo,
                                                  int n4) {
    int i = blockIdx.x * 256 + threadIdx.x;
    if (i >= n4) return;
    float4 v = src[i];
    __nv_bfloat16 h0 = __float2bfloat16(v.x);
    __nv_bfloat16 h1 = __float2bfloat16(v.y);
    __nv_bfloat16 h2 = __float2bfloat16(v.z);
    __nv_bfloat16 h3 = __float2bfloat16(v.w);
    __nv_bfloat16 l0 = __float2bfloat16(v.x - __bfloat162float(h0));
    __nv_bfloat16 l1 = __float2bfloat16(v.y - __bfloat162float(h1));
    __nv_bfloat16 l2 = __float2bfloat16(v.z - __bfloat162float(h2));
    __nv_bfloat16 l3 = __float2bfloat16(v.w - __bfloat162float(h3));
    hi[2 * i]     = __halves2bfloat162(h0, h1);
    hi[2 * i + 1] = __halves2bfloat162(h2, h3);
    lo[2 * i]     = __halves2bfloat162(l0, l1);
    lo[2 * i + 1] = __halves2bfloat162(l2, l3);
}

// ---------------------------------------------------------------------------
// Tensor-core GEMM (mma.sync bf16, 3-term split): C[M,N]=A[M,K]@W[N,K]^T fp32.
// BM=128 BN=128 BK=32, 256 thr (8 warps, 2x4), warp tile 64x32, 3-stage
// cp.async pipeline. Smem rows padded to 80B -> conflict-free ldmatrix.
// PERM=1 writes [b,h,s,d] head-major.
// ---------------------------------------------------------------------------
constexpr int ROWB = 80;                       // padded row bytes (32 bf16 data)
constexpr int TILEB = 128 * ROWB;              // 10240 B
constexpr int ASZ = 3 * 2 * TILEB;             // 3 stages x {hi,lo}
constexpr int GEMM_SMEM = 2 * ASZ;             // A + B regions
constexpr int NKT = DM / 32;                   // 32 k-chunks

template <int PERM>
__global__ __launch_bounds__(256) void gemm_mma(const __nv_bfloat16* __restrict__ Ah,
                                                const __nv_bfloat16* __restrict__ Al,
                                                const __nv_bfloat16* __restrict__ Bh,
                                                const __nv_bfloat16* __restrict__ Bl,
                                                float* __restrict__ C) {
    extern __shared__ char smem[];
    const uint32_t sb = smem_u32(smem);
    const int tid = threadIdx.x;
    const int lane = tid & 31;
    const int wid = tid >> 5;
    const int warpM = wid & 1;          // 0..1  (64 rows each)
    const int warpN = wid >> 1;         // 0..3  (32 cols each)
    const int bn = blockIdx.x;
    const int bm = blockIdx.y;
    const int rowA0 = bm * 128;
    const int rowB0 = bn * 128;

    // per-thread load coords: chunk id = tid + it*256; r=id/4, c=id%4 (16B each)
    const int lr0 = tid >> 2;           // rows for it=0 (0..63)
    const int lc = (tid & 3) * 8;       // element offset of 16B chunk

    auto load_stage = [&](int kt, int buf) {
        const size_t gkoff = (size_t)kt * 32 + lc;
#pragma unroll
        for (int it = 0; it < 2; it++) {
            int r = lr0 + it * 64;
            uint32_t so = (uint32_t)(r * ROWB + (tid & 3) * 16);
            size_t ga = (size_t)(rowA0 + r) * DM + gkoff;
            size_t gb = (size_t)(rowB0 + r) * DM + gkoff;
            uint32_t abase = sb + buf * 2 * TILEB;
            uint32_t bbase = sb + ASZ + buf * 2 * TILEB;
            cp16(abase + so,          Ah + ga);
            cp16(abase + TILEB + so,  Al + ga);
            cp16(bbase + so,          Bh + gb);
            cp16(bbase + TILEB + so,  Bl + gb);
        }
        cp_commit();
    };

    float acc[4][4][4];
#pragma unroll
    for (int i = 0; i < 4; i++)
#pragma unroll
        for (int j = 0; j < 4; j++)
#pragma unroll
            for (int e = 0; e < 4; e++) acc[i][j][e] = 0.f;

    load_stage(0, 0);
    load_stage(1, 1);

    // ldmatrix address components (element -> byte offsets within a tile)
    const int a_r = (lane & 15);              // row within 16-row tile
    const int a_c8 = (lane >> 4) * 8;         // 0 or 8 elements
    const int b_r = ((lane >> 4) * 8) + (lane & 7);   // row within 16-col pair
    const int b_c8 = ((lane >> 3) & 1) * 8;

    for (int kt = 0; kt < NKT; kt++) {
        const int buf = kt % 3;
        cp_wait1();
        __syncthreads();

        // prefetch stage kt+2 (clamped; duplicate loads into unused buffer at tail)
        int ktn = kt + 2;
        if (ktn > NKT - 1) ktn = NKT - 1;
        load_stage(ktn, (kt + 2) % 3);

        const uint32_t aHi = sb + buf * 2 * TILEB;
        const uint32_t aLo = aHi + TILEB;
        const uint32_t bHi = sb + ASZ + buf * 2 * TILEB;
        const uint32_t bLo = bHi + TILEB;
        const int mrow = warpM * 64 + a_r;
        const int nrow = warpN * 32 + b_r;

#pragma unroll
        for (int ks = 0; ks < 2; ks++) {
            uint32_t ah[4][4], al[4][4], bh[2][4], bl[2][4];
            const uint32_t acol = (uint32_t)((ks * 16 + a_c8) * 2);
            const uint32_t bcol = (uint32_t)((ks * 16 + b_c8) * 2);
#pragma unroll
            for (int mt = 0; mt < 4; mt++) {
                uint32_t ro = (uint32_t)((mrow + mt * 16) * ROWB) + acol;
                ldsm4(ah[mt], aHi + ro);
                ldsm4(al[mt], aLo + ro);
            }
#pragma unroll
            for (int np = 0; np < 2; np++) {
                uint32_t ro = (uint32_t)((nrow + np * 16) * ROWB) + bcol;
                ldsm4(bh[np], bHi + ro);
                ldsm4(bl[np], bLo + ro);
            }
#pragma unroll
            for (int mt = 0; mt < 4; mt++)
#pragma unroll
                for (int np = 0; np < 2; np++)
#pragma unroll
                    for (int ns = 0; ns < 2; ns++) {
                        float* c = acc[mt][np * 2 + ns];
                        mma16816(c, ah[mt], &bh[np][ns * 2]);
                        mma16816(c, ah[mt], &bl[np][ns * 2]);
                        mma16816(c, al[mt], &bh[np][ns * 2]);
                    }
        }
        __syncthreads();
    }

    // Epilogue: frag (m16n8): c0,c1 -> (row, col..col+1); c2,c3 -> (row+8, ..)
    const int rbase = bm * 128 + warpM * 64 + (lane >> 2);
    const int cbase = bn * 128 + warpN * 32 + (lane & 3) * 2;
#pragma unroll
    for (int mt = 0; mt < 4; mt++) {
#pragma unroll
        for (int nt = 0; nt < 4; nt++) {
            int row = rbase + mt * 16;
            int col = cbase + nt * 8;
#pragma unroll
            for (int half = 0; half < 2; half++) {
                int r = row + half * 8;
                float2 val = make_float2(acc[mt][nt][half * 2],
                                         acc[mt][nt][half * 2 + 1]);
                if (PERM == 0) {
                    *(float2*)(C + (size_t)r * DM + col) = val;
                } else {
                    int b_ = r >> 11;
                    int s_ = r & 2047;
                    int h_ = col >> 6;
                    int d_ = col & 63;
                    *(float2*)(C + ((((size_t)b_ * H + h_) * S + s_) << 6) + d_) = val;
                }
            }
        }
    }
}

// ---------------------------------------------------------------------------
// Causal flash attention, fp32 (unchanged from R1 — passed at rel_err 1.2e-6).
// ---------------------------------------------------------------------------
__global__ __launch_bounds__(128) void attn_kernel(const float* __restrict__ Q,
                                                   const float* __restrict__ K,
                                                   const float* __restrict__ V,
                                                   float* __restrict__ O) {
    __shared__ __align__(16) float ksh[64][64];
    __shared__ __align__(16) float vsh[64][64];

    const int tid = threadIdx.x;
    const int qt = blockIdx.x;
    const int h  = blockIdx.y;
    const int b  = blockIdx.z;
    const int qi = qt * 128 + tid;

    const size_t headoff = (((size_t)b * H + h) * S) * DH;
    const float* qbase = Q + headoff;
    const float* kbase = K + headoff;
    const float* vbase = V + headoff;

    float q[64];
    {
        const float4* q4 = (const float4*)(qbase + (size_t)qi * DH);
#pragma unroll
        for (int d4 = 0; d4 < 16; d4++) {
            float4 t = q4[d4];
            q[d4 * 4 + 0] = t.x; q[d4 * 4 + 1] = t.y;
            q[d4 * 4 + 2] = t.z; q[d4 * 4 + 3] = t.w;
        }
    }

    float acc[64];
#pragma unroll
    for (int d = 0; d < 64; d++) acc[d] = 0.f;
    float mval = -1e30f;
    float lsum = 0.f;

    const int nkt = (qt * 128 + 128) / 64;

    for (int kt = 0; kt < nkt; kt++) {
        const float4* ksrc = (const float4*)(kbase + (size_t)kt * 64 * DH);
        const float4* vsrc = (const float4*)(vbase + (size_t)kt * 64 * DH);
        float4* kdst = (float4*)&ksh[0][0];
        float4* vdst = (float4*)&vsh[0][0];
#pragma unroll
        for (int i = 0; i < 8; i++) {
            kdst[tid + i * 128] = ksrc[tid + i * 128];
            vdst[tid + i * 128] = vsrc[tid + i * 128];
        }
        __syncthreads();

        int rel = qi - kt * 64;
        int jend = rel >= 63 ? 64 : (rel + 1);
        if (jend < 0) jend = 0;

        for (int j = 0; j < jend; j++) {
            const float4* kr = (const float4*)&ksh[j][0];
            float s = 0.f;
#pragma unroll
            for (int d4 = 0; d4 < 16; d4++) {
                float4 kv = kr[d4];
                s += q[d4 * 4 + 0] * kv.x + q[d4 * 4 + 1] * kv.y +
                     q[d4 * 4 + 2] * kv.z + q[d4 * 4 + 3] * kv.w;
            }
            s *= 0.125f;

            const float4* vr = (const float4*)&vsh[j][0];
            if (s <= mval) {
                float p = __expf(s - mval);
                lsum += p;
#pragma unroll
                for (int d4 = 0; d4 < 16; d4++) {
                    float4 vv = vr[d4];
                    acc[d4 * 4 + 0] += p * vv.x;
                    acc[d4 * 4 + 1] += p * vv.y;
                    acc[d4 * 4 + 2] += p * vv.z;
                    acc[d4 * 4 + 3] += p * vv.w;
                }
            } else {
                float sc = __expf(mval - s);
                mval = s;
                lsum = lsum * sc + 1.f;
#pragma unroll
                for (int d4 = 0; d4 < 16; d4++) {
                    float4 vv = vr[d4];
                    acc[d4 * 4 + 0] = acc[d4 * 4 + 0] * sc + vv.x;
                    acc[d4 * 4 + 1] = acc[d4 * 4 + 1] * sc + vv.y;
                    acc[d4 * 4 + 2] = acc[d4 * 4 + 2] * sc + vv.z;
                    acc[d4 * 4 + 3] = acc[d4 * 4 + 3] * sc + vv.w;
                }
            }
        }
        __syncthreads();
    }

    const float inv = 1.f / lsum;
    float4* o4 = (float4*)(O + ((size_t)b * S + qi) * DM + h * DH);
#pragma unroll
    for (int d4 = 0; d4 < 16; d4++) {
        o4[d4] = make_float4(acc[d4 * 4 + 0] * inv, acc[d4 * 4 + 1] * inv,
                             acc[d4 * 4 + 2] * inv, acc[d4 * 4 + 3] * inv);
    }
}

// ---------------------------------------------------------------------------
extern "C" void kernel_launch(void* const* d_in, const int* in_sizes, int n_in,
                              void* d_out, int out_size) {
    const float* w[4] = {nullptr, nullptr, nullptr, nullptr};
    const float* x = nullptr;
    int wn = 0;
    for (int i = 0; i < n_in; i++) {
        if (in_sizes[i] == DM * DM && wn < 4) {
            w[wn++] = (const float*)d_in[i];
        } else if (in_sizes[i] == B * S * DM) {
            x = (const float*)d_in[i];
        }
    }

    float *q, *k, *v, *ao;
    __nv_bfloat16 *xhi, *xlo, *whi, *wlo, *aohi, *aolo;
    cudaGetSymbolAddress((void**)&q, g_q);
    cudaGetSymbolAddress((void**)&k, g_k);
    cudaGetSymbolAddress((void**)&v, g_v);
    cudaGetSymbolAddress((void**)&ao, g_ao);
    cudaGetSymbolAddress((void**)&xhi, g_xhi);
    cudaGetSymbolAddress((void**)&xlo, g_xlo);
    cudaGetSymbolAddress((void**)&whi, g_whi);
    cudaGetSymbolAddress((void**)&wlo, g_wlo);
    cudaGetSymbolAddress((void**)&aohi, g_aohi);
    cudaGetSymbolAddress((void**)&aolo, g_aolo);

    cudaFuncSetAttribute(gemm_mma<0>, cudaFuncAttributeMaxDynamicSharedMemorySize, GEMM_SMEM);
    cudaFuncSetAttribute(gemm_mma<1>, cudaFuncAttributeMaxDynamicSharedMemorySize, GEMM_SMEM);

    const int xn4 = (M * DM) / 4;
    const int wn4 = (DM * DM) / 4;
    split_bf16<<<(xn4 + 255) / 256, 256>>>((const float4*)x,
                                           (__nv_bfloat162*)xhi, (__nv_bfloat162*)xlo, xn4);
    for (int i = 0; i < 4; i++) {
        split_bf16<<<(wn4 + 255) / 256, 256>>>((const float4*)w[i],
                                               (__nv_bfloat162*)(whi + (size_t)i * DM * DM),
                                               (__nv_bfloat162*)(wlo + (size_t)i * DM * DM), wn4);
    }

    dim3 ggrid(DM / 128, M / 128);  // (8, 64)
    gemm_mma<1><<<ggrid, 256, GEMM_SMEM>>>(xhi, xlo, whi + 0 * (size_t)DM * DM,
                                           wlo + 0 * (size_t)DM * DM, q);
    gemm_mma<1><<<ggrid, 256, GEMM_SMEM>>>(xhi, xlo, whi + 1 * (size_t)DM * DM,
                                           wlo + 1 * (size_t)DM * DM, k);
    gemm_mma<1><<<ggrid, 256, GEMM_SMEM>>>(xhi, xlo, whi + 2 * (size_t)DM * DM,
                                           wlo + 2 * (size_t)DM * DM, v);

    dim3 agrid(S / 128, H, B);  // (16, 16, 4)
    attn_kernel<<<agrid, 128>>>(q, k, v, ao);

    split_bf16<<<(xn4 + 255) / 256, 256>>>((const float4*)ao,
                                           (__nv_bfloat162*)aohi, (__nv_bfloat162*)aolo, xn4);
    gemm_mma<0><<<ggrid, 256, GEMM_SMEM>>>(aohi, aolo, whi + 3 * (size_t)DM * DM,
                                           wlo + 3 * (size_t)DM * DM, (float*)d_out);
}

// round 4
// speedup vs baseline: 2.8131x; 2.1197x over previous
#include <cuda_runtime.h>
#include <cuda_bf16.h>
#include <cstdint>
#include <math.h>

// Problem constants
constexpr int DM = 1024;   // d_model
constexpr int H  = 16;     // heads
constexpr int DH = 64;     // head dim
constexpr int B  = 4;      // batch
constexpr int S  = 2048;   // seq len
constexpr int M  = B * S;  // 8192 rows

// Scratch (allocation-free rule: __device__ globals)
__device__ __nv_bfloat16 g_xhi[(size_t)M * DM];
__device__ __nv_bfloat16 g_xlo[(size_t)M * DM];
__device__ __nv_bfloat16 g_whi[(size_t)4 * DM * DM];
__device__ __nv_bfloat16 g_wlo[(size_t)4 * DM * DM];
__device__ __nv_bfloat16 g_qhi[(size_t)M * DM];
__device__ __nv_bfloat16 g_qlo[(size_t)M * DM];
__device__ __nv_bfloat16 g_khi[(size_t)M * DM];
__device__ __nv_bfloat16 g_klo[(size_t)M * DM];
__device__ __nv_bfloat16 g_vhi[(size_t)M * DM];
__device__ __nv_bfloat16 g_vlo[(size_t)M * DM];
__device__ __nv_bfloat16 g_aohi[(size_t)M * DM];
__device__ __nv_bfloat16 g_aolo[(size_t)M * DM];

// ---------------------------------------------------------------------------
// PTX helpers (compute_103-safe: mma.sync / ldmatrix / cp.async only)
// ---------------------------------------------------------------------------
__device__ __forceinline__ uint32_t smem_u32(const void* p) {
    uint32_t a;
    asm("{ .reg .u64 t; cvta.to.shared.u64 t, %1; cvt.u32.u64 %0, t; }"
        : "=r"(a) : "l"(p));
    return a;
}
__device__ __forceinline__ void cp16(uint32_t saddr, const void* gaddr) {
    asm volatile("cp.async.cg.shared.global [%0], [%1], 16;"
                 :: "r"(saddr), "l"(gaddr) : "memory");
}
__device__ __forceinline__ void cp_commit() {
    asm volatile("cp.async.commit_group;" ::: "memory");
}
template <int N>
__device__ __forceinline__ void cp_waitg() {
    asm volatile("cp.async.wait_group %0;" :: "n"(N) : "memory");
}
__device__ __forceinline__ void ldsm4(uint32_t* r, uint32_t addr) {
    asm volatile("ldmatrix.sync.aligned.m8n8.x4.shared.b16 {%0,%1,%2,%3}, [%4];"
                 : "=r"(r[0]), "=r"(r[1]), "=r"(r[2]), "=r"(r[3]) : "r"(addr));
}
__device__ __forceinline__ void ldsm4t(uint32_t* r, uint32_t addr) {
    asm volatile("ldmatrix.sync.aligned.m8n8.x4.trans.shared.b16 {%0,%1,%2,%3}, [%4];"
                 : "=r"(r[0]), "=r"(r[1]), "=r"(r[2]), "=r"(r[3]) : "r"(addr));
}
__device__ __forceinline__ void mma16816(float* c, const uint32_t* a, const uint32_t* b) {
    asm volatile(
        "mma.sync.aligned.m16n8k16.row.col.f32.bf16.bf16.f32 "
        "{%0,%1,%2,%3}, {%4,%5,%6,%7}, {%8,%9}, {%0,%1,%2,%3};"
        : "+f"(c[0]), "+f"(c[1]), "+f"(c[2]), "+f"(c[3])
        : "r"(a[0]), "r"(a[1]), "r"(a[2]), "r"(a[3]), "r"(b[0]), "r"(b[1]));
}
// pack 2 floats -> bf16x2, hi-part (truncation) / lo-part (residual, RN)
__device__ __forceinline__ uint32_t pk_hi2(float a, float b) {
    return __byte_perm(__float_as_uint(a), __float_as_uint(b), 0x7632);
}
__device__ __forceinline__ uint32_t pk_lo2(float a, float b) {
    float la = a - __uint_as_float(__float_as_uint(a) & 0xFFFF0000u);
    float lb = b - __uint_as_float(__float_as_uint(b) & 0xFFFF0000u);
    uint32_t r;
    asm("cvt.rn.bf16x2.f32 %0, %1, %2;" : "=r"(r) : "f"(lb), "f"(la));
    return r;
}

// ---------------------------------------------------------------------------
// fp32 -> (bf16 hi, bf16 lo) split (inputs x and weights)
// ---------------------------------------------------------------------------
__global__ __launch_bounds__(256) void split_bf16(const float4* __restrict__ src,
                                                  uint32_t* __restrict__ hi,
                                                  uint32_t* __restrict__ lo,
                                                  int n4) {
    int i = blockIdx.x * 256 + threadIdx.x;
    if (i >= n4) return;
    float4 v = src[i];
    hi[2 * i]     = pk_hi2(v.x, v.y);
    hi[2 * i + 1] = pk_hi2(v.z, v.w);
    lo[2 * i]     = pk_lo2(v.x, v.y);
    lo[2 * i + 1] = pk_lo2(v.z, v.w);
}

// ---------------------------------------------------------------------------
// Tensor-core GEMM (mma.sync bf16, 3-term split): C[M,N]=A[M,K]@W[N,K]^T fp32.
// BM=128 BN=128 BK=32, 256 thr (8 warps 2x4), warp tile 64x32, 3-stage
// cp.async pipeline. OUTBF=1: write bf16 hi/lo in [b,h,s,d] head-major.
// ---------------------------------------------------------------------------
constexpr int ROWB = 80;
constexpr int TILEB = 128 * ROWB;
constexpr int ASZ = 3 * 2 * TILEB;
constexpr int GEMM_SMEM = 2 * ASZ;
constexpr int NKT = DM / 32;

template <int OUTBF>
__global__ __launch_bounds__(256) void gemm_mma(const __nv_bfloat16* __restrict__ Ah,
                                                const __nv_bfloat16* __restrict__ Al,
                                                const __nv_bfloat16* __restrict__ Bh,
                                                const __nv_bfloat16* __restrict__ Bl,
                                                float* __restrict__ C,
                                                __nv_bfloat16* __restrict__ Chi,
                                                __nv_bfloat16* __restrict__ Clo) {
    extern __shared__ char smem[];
    const uint32_t sb = smem_u32(smem);
    const int tid = threadIdx.x;
    const int lane = tid & 31;
    const int wid = tid >> 5;
    const int warpM = wid & 1;
    const int warpN = wid >> 1;
    const int bn = blockIdx.x;
    const int bm = blockIdx.y;
    const int rowA0 = bm * 128;
    const int rowB0 = bn * 128;

    const int lr0 = tid >> 2;
    const int lc = (tid & 3) * 8;

    auto load_stage = [&](int kt, int buf) {
        const size_t gkoff = (size_t)kt * 32 + lc;
#pragma unroll
        for (int it = 0; it < 2; it++) {
            int r = lr0 + it * 64;
            uint32_t so = (uint32_t)(r * ROWB + (tid & 3) * 16);
            size_t ga = (size_t)(rowA0 + r) * DM + gkoff;
            size_t gb = (size_t)(rowB0 + r) * DM + gkoff;
            uint32_t abase = sb + buf * 2 * TILEB;
            uint32_t bbase = sb + ASZ + buf * 2 * TILEB;
            cp16(abase + so,          Ah + ga);
            cp16(abase + TILEB + so,  Al + ga);
            cp16(bbase + so,          Bh + gb);
            cp16(bbase + TILEB + so,  Bl + gb);
        }
        cp_commit();
    };

    float acc[4][4][4];
#pragma unroll
    for (int i = 0; i < 4; i++)
#pragma unroll
        for (int j = 0; j < 4; j++)
#pragma unroll
            for (int e = 0; e < 4; e++) acc[i][j][e] = 0.f;

    load_stage(0, 0);
    load_stage(1, 1);

    const int a_r = (lane & 15);
    const int a_c8 = (lane >> 4) * 8;
    const int b_r = ((lane >> 4) * 8) + (lane & 7);
    const int b_c8 = ((lane >> 3) & 1) * 8;

    for (int kt = 0; kt < NKT; kt++) {
        const int buf = kt % 3;
        cp_waitg<1>();
        __syncthreads();

        int ktn = kt + 2;
        if (ktn > NKT - 1) ktn = NKT - 1;
        load_stage(ktn, (kt + 2) % 3);

        const uint32_t aHi = sb + buf * 2 * TILEB;
        const uint32_t aLo = aHi + TILEB;
        const uint32_t bHi = sb + ASZ + buf * 2 * TILEB;
        const uint32_t bLo = bHi + TILEB;
        const int mrow = warpM * 64 + a_r;
        const int nrow = warpN * 32 + b_r;

#pragma unroll
        for (int ks = 0; ks < 2; ks++) {
            uint32_t ah[4][4], al[4][4], bh[2][4], bl[2][4];
            const uint32_t acol = (uint32_t)((ks * 16 + a_c8) * 2);
            const uint32_t bcol = (uint32_t)((ks * 16 + b_c8) * 2);
#pragma unroll
            for (int mt = 0; mt < 4; mt++) {
                uint32_t ro = (uint32_t)((mrow + mt * 16) * ROWB) + acol;
                ldsm4(ah[mt], aHi + ro);
                ldsm4(al[mt], aLo + ro);
            }
#pragma unroll
            for (int np = 0; np < 2; np++) {
                uint32_t ro = (uint32_t)((nrow + np * 16) * ROWB) + bcol;
                ldsm4(bh[np], bHi + ro);
                ldsm4(bl[np], bLo + ro);
            }
#pragma unroll
            for (int mt = 0; mt < 4; mt++)
#pragma unroll
                for (int np = 0; np < 2; np++)
#pragma unroll
                    for (int ns = 0; ns < 2; ns++) {
                        float* c = acc[mt][np * 2 + ns];
                        mma16816(c, ah[mt], &bh[np][ns * 2]);
                        mma16816(c, ah[mt], &bl[np][ns * 2]);
                        mma16816(c, al[mt], &bh[np][ns * 2]);
                    }
        }
        __syncthreads();
    }

    const int rbase = bm * 128 + warpM * 64 + (lane >> 2);
    const int cbase = bn * 128 + warpN * 32 + (lane & 3) * 2;
#pragma unroll
    for (int mt = 0; mt < 4; mt++) {
#pragma unroll
        for (int nt = 0; nt < 4; nt++) {
            int row = rbase + mt * 16;
            int col = cbase + nt * 8;
#pragma unroll
            for (int half = 0; half < 2; half++) {
                int r = row + half * 8;
                float vx = acc[mt][nt][half * 2];
                float vy = acc[mt][nt][half * 2 + 1];
                if (OUTBF == 0) {
                    *(float2*)(C + (size_t)r * DM + col) = make_float2(vx, vy);
                } else {
                    int b_ = r >> 11;
                    int s_ = r & 2047;
                    int h_ = col >> 6;
                    int d_ = col & 63;
                    size_t idx = ((((size_t)b_ * H + h_) * S + s_) << 6) + d_;
                    *(uint32_t*)(Chi + idx) = pk_hi2(vx, vy);
                    *(uint32_t*)(Clo + idx) = pk_lo2(vx, vy);
                }
            }
        }
    }
}

// ---------------------------------------------------------------------------
// Tensor-core causal flash attention, bf16 split (fp32-accurate).
// Block: 128 thr (4 warps), 64 queries per CTA, KV tiles of 64, double-buffered
// cp.async. Per warp: 16 query rows. Writes AO as bf16 hi/lo [b,s,h*64+d].
// ---------------------------------------------------------------------------
constexpr int AROWB = 144;              // 64 bf16 = 128B data + 16B pad
constexpr int ATILE = 64 * AROWB;       // 9216
constexpr int ASTG = 4 * ATILE;         // Kh, Kl, Vh, Vl
constexpr int ATT_SMEM = 2 * ASTG;      // 73728

__global__ __launch_bounds__(128) void attn_mma(
    const __nv_bfloat16* __restrict__ Qh, const __nv_bfloat16* __restrict__ Ql,
    const __nv_bfloat16* __restrict__ Kh, const __nv_bfloat16* __restrict__ Kl,
    const __nv_bfloat16* __restrict__ Vh, const __nv_bfloat16* __restrict__ Vl,
    __nv_bfloat16* __restrict__ AOh, __nv_bfloat16* __restrict__ AOl) {
    extern __shared__ char smem[];
    const uint32_t sb = smem_u32(smem);
    const int tid = threadIdx.x;
    const int lane = tid & 31;
    const int wid = tid >> 5;
    const int qt = blockIdx.x;
    const int h = blockIdx.y;
    const int b = blockIdx.z;
    const size_t hb = (((size_t)b * H + h) * S) * DH;

    // Stage Q (64x64 hi/lo) into buffer 0's Kh/Kl regions, extract to regs
#pragma unroll
    for (int i = 0; i < 4; i++) {
        int id = tid + i * 128;
        int r = id >> 3, c = id & 7;
        uint32_t so = (uint32_t)(r * AROWB + c * 16);
        size_t g = hb + (size_t)(qt * 64 + r) * DH + c * 8;
        cp16(sb + so, Qh + g);
        cp16(sb + ATILE + so, Ql + g);
    }
    cp_commit();
    cp_waitg<0>();
    __syncthreads();

    uint32_t qh[4][4], ql[4][4];
    {
        int row = wid * 16 + (lane & 15);
#pragma unroll
        for (int ks = 0; ks < 4; ks++) {
            uint32_t off = (uint32_t)(row * AROWB + (ks * 16 + (lane >> 4) * 8) * 2);
            ldsm4(qh[ks], sb + off);
            ldsm4(ql[ks], sb + ATILE + off);
        }
    }
    __syncthreads();

    float ov[8][4];
#pragma unroll
    for (int o = 0; o < 8; o++)
#pragma unroll
        for (int e = 0; e < 4; e++) ov[o][e] = 0.f;
    float m0 = -1e30f, m1 = -1e30f, l0 = 0.f, l1 = 0.f;

    const int nkt = qt + 1;

    auto load_kv = [&](int kt, int bufi) {
        uint32_t base = sb + bufi * ASTG;
#pragma unroll
        for (int i = 0; i < 4; i++) {
            int id = tid + i * 128;
            int r = id >> 3, c = id & 7;
            uint32_t so = (uint32_t)(r * AROWB + c * 16);
            size_t g = hb + (size_t)(kt * 64 + r) * DH + c * 8;
            cp16(base + so,             Kh + g);
            cp16(base + ATILE + so,     Kl + g);
            cp16(base + 2 * ATILE + so, Vh + g);
            cp16(base + 3 * ATILE + so, Vl + g);
        }
        cp_commit();
    };
    load_kv(0, 0);

    for (int kt = 0; kt < nkt; kt++) {
        const int buf = kt & 1;
        if (kt + 1 < nkt) { load_kv(kt + 1, buf ^ 1); cp_waitg<1>(); }
        else              { cp_waitg<0>(); }
        __syncthreads();
        const uint32_t kb = sb + buf * ASTG;

        // S = Qh*Kh + Ql*Kh + Qh*Kl
        float sf[8][4];
#pragma unroll
        for (int o = 0; o < 8; o++)
#pragma unroll
            for (int e = 0; e < 4; e++) sf[o][e] = 0.f;

#pragma unroll
        for (int ks = 0; ks < 4; ks++) {
#pragma unroll
            for (int np = 0; np < 4; np++) {
                uint32_t kh4[4], kl4[4];
                uint32_t ro = (uint32_t)(
                    (np * 16 + (lane >> 4) * 8 + (lane & 7)) * AROWB +
                    (ks * 16 + ((lane >> 3) & 1) * 8) * 2);
                ldsm4(kh4, kb + ro);
                ldsm4(kl4, kb + ATILE + ro);
#pragma unroll
                for (int ns = 0; ns < 2; ns++) {
                    float* c = sf[np * 2 + ns];
                    mma16816(c, qh[ks], &kh4[ns * 2]);
                    mma16816(c, qh[ks], &kl4[ns * 2]);
                    mma16816(c, ql[ks], &kh4[ns * 2]);
                }
            }
        }

        // online softmax (fp32)
        const bool diag = (kt == qt);
        const int r0 = lane >> 2;
        const int q0 = wid * 16 + r0;
        const int q1 = q0 + 8;
        float mx0 = -1e30f, mx1 = -1e30f;
#pragma unroll
        for (int o = 0; o < 8; o++) {
#pragma unroll
            for (int e = 0; e < 2; e++) {
                int keyl = o * 8 + (lane & 3) * 2 + e;
                float v0 = sf[o][e] * 0.125f;
                float v1 = sf[o][2 + e] * 0.125f;
                if (diag && keyl > q0) v0 = -1e30f;
                if (diag && keyl > q1) v1 = -1e30f;
                sf[o][e] = v0;
                sf[o][2 + e] = v1;
                mx0 = fmaxf(mx0, v0);
                mx1 = fmaxf(mx1, v1);
            }
        }
        mx0 = fmaxf(mx0, __shfl_xor_sync(0xffffffffu, mx0, 1));
        mx0 = fmaxf(mx0, __shfl_xor_sync(0xffffffffu, mx0, 2));
        mx1 = fmaxf(mx1, __shfl_xor_sync(0xffffffffu, mx1, 1));
        mx1 = fmaxf(mx1, __shfl_xor_sync(0xffffffffu, mx1, 2));
        const float mn0 = fmaxf(m0, mx0);
        const float mn1 = fmaxf(m1, mx1);
        const float es0 = __expf(m0 - mn0);
        const float es1 = __expf(m1 - mn1);
        m0 = mn0; m1 = mn1;

        float rs0 = 0.f, rs1 = 0.f;
#pragma unroll
        for (int o = 0; o < 8; o++) {
#pragma unroll
            for (int e = 0; e < 2; e++) {
                float p0 = __expf(sf[o][e] - mn0);
                float p1 = __expf(sf[o][2 + e] - mn1);
                sf[o][e] = p0;
                sf[o][2 + e] = p1;
                rs0 += p0;
                rs1 += p1;
            }
        }
        rs0 += __shfl_xor_sync(0xffffffffu, rs0, 1);
        rs0 += __shfl_xor_sync(0xffffffffu, rs0, 2);
        rs1 += __shfl_xor_sync(0xffffffffu, rs1, 1);
        rs1 += __shfl_xor_sync(0xffffffffu, rs1, 2);
        l0 = l0 * es0 + rs0;
        l1 = l1 * es1 + rs1;
#pragma unroll
        for (int o = 0; o < 8; o++) {
            ov[o][0] *= es0; ov[o][1] *= es0;
            ov[o][2] *= es1; ov[o][3] *= es1;
        }

        // O += Ph*Vh + Pl*Vh + Ph*Vl  (V via ldmatrix.trans)
#pragma unroll
        for (int kp = 0; kp < 4; kp++) {
            uint32_t pah[4], pal[4];
            pah[0] = pk_hi2(sf[2 * kp][0], sf[2 * kp][1]);
            pah[1] = pk_hi2(sf[2 * kp][2], sf[2 * kp][3]);
            pah[2] = pk_hi2(sf[2 * kp + 1][0], sf[2 * kp + 1][1]);
            pah[3] = pk_hi2(sf[2 * kp + 1][2], sf[2 * kp + 1][3]);
            pal[0] = pk_lo2(sf[2 * kp][0], sf[2 * kp][1]);
            pal[1] = pk_lo2(sf[2 * kp][2], sf[2 * kp][3]);
            pal[2] = pk_lo2(sf[2 * kp + 1][0], sf[2 * kp + 1][1]);
            pal[3] = pk_lo2(sf[2 * kp + 1][2], sf[2 * kp + 1][3]);
#pragma unroll
            for (int dp = 0; dp < 4; dp++) {
                uint32_t bvh[4], bvl[4];
                uint32_t vo = (uint32_t)(
                    (kp * 16 + (lane & 15)) * AROWB +
                    (dp * 16 + (lane >> 4) * 8) * 2);
                ldsm4t(bvh, kb + 2 * ATILE + vo);
                ldsm4t(bvl, kb + 3 * ATILE + vo);
#pragma unroll
                for (int ns = 0; ns < 2; ns++) {
                    float* o_ = ov[dp * 2 + ns];
                    mma16816(o_, pah, &bvh[ns * 2]);
                    mma16816(o_, pal, &bvh[ns * 2]);
                    mma16816(o_, pah, &bvl[ns * 2]);
                }
            }
        }
        __syncthreads();
    }

    // epilogue: normalize, split to bf16 hi/lo, write [b, s, h*64 + d]
    const float inv0 = 1.f / l0;
    const float inv1 = 1.f / l1;
    const int s0 = qt * 64 + wid * 16 + (lane >> 2);
    const size_t row0 = ((size_t)b * S + s0) * DM + h * DH;
    const size_t row1 = row0 + (size_t)8 * DM;
#pragma unroll
    for (int o = 0; o < 8; o++) {
        int d = o * 8 + (lane & 3) * 2;
        float x0 = ov[o][0] * inv0, y0 = ov[o][1] * inv0;
        float x1 = ov[o][2] * inv1, y1 = ov[o][3] * inv1;
        *(uint32_t*)(AOh + row0 + d) = pk_hi2(x0, y0);
        *(uint32_t*)(AOl + row0 + d) = pk_lo2(x0, y0);
        *(uint32_t*)(AOh + row1 + d) = pk_hi2(x1, y1);
        *(uint32_t*)(AOl + row1 + d) = pk_lo2(x1, y1);
    }
}

// ---------------------------------------------------------------------------
extern "C" void kernel_launch(void* const* d_in, const int* in_sizes, int n_in,
                              void* d_out, int out_size) {
    const float* w[4] = {nullptr, nullptr, nullptr, nullptr};
    const float* x = nullptr;
    int wn = 0;
    for (int i = 0; i < n_in; i++) {
        if (in_sizes[i] == DM * DM && wn < 4) {
            w[wn++] = (const float*)d_in[i];
        } else if (in_sizes[i] == B * S * DM) {
            x = (const float*)d_in[i];
        }
    }

    __nv_bfloat16 *xhi, *xlo, *whi, *wlo;
    __nv_bfloat16 *qhi, *qlo, *khi, *klo, *vhi, *vlo, *aohi, *aolo;
    cudaGetSymbolAddress((void**)&xhi, g_xhi);
    cudaGetSymbolAddress((void**)&xlo, g_xlo);
    cudaGetSymbolAddress((void**)&whi, g_whi);
    cudaGetSymbolAddress((void**)&wlo, g_wlo);
    cudaGetSymbolAddress((void**)&qhi, g_qhi);
    cudaGetSymbolAddress((void**)&qlo, g_qlo);
    cudaGetSymbolAddress((void**)&khi, g_khi);
    cudaGetSymbolAddress((void**)&klo, g_klo);
    cudaGetSymbolAddress((void**)&vhi, g_vhi);
    cudaGetSymbolAddress((void**)&vlo, g_vlo);
    cudaGetSymbolAddress((void**)&aohi, g_aohi);
    cudaGetSymbolAddress((void**)&aolo, g_aolo);

    cudaFuncSetAttribute(gemm_mma<0>, cudaFuncAttributeMaxDynamicSharedMemorySize, GEMM_SMEM);
    cudaFuncSetAttribute(gemm_mma<1>, cudaFuncAttributeMaxDynamicSharedMemorySize, GEMM_SMEM);
    cudaFuncSetAttribute(attn_mma, cudaFuncAttributeMaxDynamicSharedMemorySize, ATT_SMEM);

    const int xn4 = (M * DM) / 4;
    const int wn4 = (DM * DM) / 4;
    split_bf16<<<(xn4 + 255) / 256, 256>>>((const float4*)x,
                                           (uint32_t*)xhi, (uint32_t*)xlo, xn4);
    for (int i = 0; i < 4; i++) {
        split_bf16<<<(wn4 + 255) / 256, 256>>>((const float4*)w[i],
                                               (uint32_t*)(whi + (size_t)i * DM * DM),
                                               (uint32_t*)(wlo + (size_t)i * DM * DM), wn4);
    }

    dim3 ggrid(DM / 128, M / 128);  // (8, 64)
    gemm_mma<1><<<ggrid, 256, GEMM_SMEM>>>(xhi, xlo, whi + 0 * (size_t)DM * DM,
                                           wlo + 0 * (size_t)DM * DM, nullptr, qhi, qlo);
    gemm_mma<1><<<ggrid, 256, GEMM_SMEM>>>(xhi, xlo, whi + 1 * (size_t)DM * DM,
                                           wlo + 1 * (size_t)DM * DM, nullptr, khi, klo);
    gemm_mma<1><<<ggrid, 256, GEMM_SMEM>>>(xhi, xlo, whi + 2 * (size_t)DM * DM,
                                           wlo + 2 * (size_t)DM * DM, nullptr, vhi, vlo);

    dim3 agrid(S / 64, H, B);  // (32, 16, 4)
    attn_mma<<<agrid, 128, ATT_SMEM>>>(qhi, qlo, khi, klo, vhi, vlo, aohi, aolo);

    gemm_mma<0><<<ggrid, 256, GEMM_SMEM>>>(aohi, aolo, whi + 3 * (size_t)DM * DM,
                                           wlo + 3 * (size_t)DM * DM, (float*)d_out,
                                           nullptr, nullptr);
}

// round 5
// speedup vs baseline: 3.8145x; 1.3560x over previous
#include <cuda_runtime.h>
#include <cuda_bf16.h>
#include <cuda_fp16.h>
#include <cstdint>
#include <math.h>

// Problem constants
constexpr int DM = 1024;   // d_model
constexpr int H  = 16;     // heads
constexpr int DH = 64;     // head dim
constexpr int B  = 4;      // batch
constexpr int S  = 2048;   // seq len
constexpr int M  = B * S;  // 8192 rows

// Scratch (allocation-free rule: __device__ globals)
__device__ __half g_xhi[(size_t)M * DM];
__device__ __half g_xlo[(size_t)M * DM];
__device__ __half g_whi[(size_t)4 * DM * DM];          // weights: fp16 hi only
__device__ __nv_bfloat16 g_qkvhi[(size_t)3 * M * DM];  // q,k,v head-major bf16
__device__ __nv_bfloat16 g_qkvlo[(size_t)3 * M * DM];
__device__ __half g_aohi[(size_t)M * DM];
__device__ __half g_aolo[(size_t)M * DM];

// ---------------------------------------------------------------------------
// PTX helpers (compute_103-safe)
// ---------------------------------------------------------------------------
__device__ __forceinline__ uint32_t smem_u32(const void* p) {
    uint32_t a;
    asm("{ .reg .u64 t; cvta.to.shared.u64 t, %1; cvt.u32.u64 %0, t; }"
        : "=r"(a) : "l"(p));
    return a;
}
__device__ __forceinline__ void cp16(uint32_t saddr, const void* gaddr) {
    asm volatile("cp.async.cg.shared.global [%0], [%1], 16;"
                 :: "r"(saddr), "l"(gaddr) : "memory");
}
__device__ __forceinline__ void cp_commit() {
    asm volatile("cp.async.commit_group;" ::: "memory");
}
template <int N>
__device__ __forceinline__ void cp_waitg() {
    asm volatile("cp.async.wait_group %0;" :: "n"(N) : "memory");
}
__device__ __forceinline__ void ldsm4(uint32_t* r, uint32_t addr) {
    asm volatile("ldmatrix.sync.aligned.m8n8.x4.shared.b16 {%0,%1,%2,%3}, [%4];"
                 : "=r"(r[0]), "=r"(r[1]), "=r"(r[2]), "=r"(r[3]) : "r"(addr));
}
__device__ __forceinline__ void ldsm4t(uint32_t* r, uint32_t addr) {
    asm volatile("ldmatrix.sync.aligned.m8n8.x4.trans.shared.b16 {%0,%1,%2,%3}, [%4];"
                 : "=r"(r[0]), "=r"(r[1]), "=r"(r[2]), "=r"(r[3]) : "r"(addr));
}
// bf16 mma (attention)
__device__ __forceinline__ void mma16816(float* c, const uint32_t* a, const uint32_t* b) {
    asm volatile(
        "mma.sync.aligned.m16n8k16.row.col.f32.bf16.bf16.f32 "
        "{%0,%1,%2,%3}, {%4,%5,%6,%7}, {%8,%9}, {%0,%1,%2,%3};"
        : "+f"(c[0]), "+f"(c[1]), "+f"(c[2]), "+f"(c[3])
        : "r"(a[0]), "r"(a[1]), "r"(a[2]), "r"(a[3]), "r"(b[0]), "r"(b[1]));
}
// fp16 mma (projection GEMMs)
__device__ __forceinline__ void mma16816h(float* c, const uint32_t* a, const uint32_t* b) {
    asm volatile(
        "mma.sync.aligned.m16n8k16.row.col.f32.f16.f16.f32 "
        "{%0,%1,%2,%3}, {%4,%5,%6,%7}, {%8,%9}, {%0,%1,%2,%3};"
        : "+f"(c[0]), "+f"(c[1]), "+f"(c[2]), "+f"(c[3])
        : "r"(a[0]), "r"(a[1]), "r"(a[2]), "r"(a[3]), "r"(b[0]), "r"(b[1]));
}
// bf16 packers (truncation hi / RN residual lo)
__device__ __forceinline__ uint32_t pk_hi2(float a, float b) {
    return __byte_perm(__float_as_uint(a), __float_as_uint(b), 0x7632);
}
__device__ __forceinline__ uint32_t pk_lo2(float a, float b) {
    float la = a - __uint_as_float(__float_as_uint(a) & 0xFFFF0000u);
    float lb = b - __uint_as_float(__float_as_uint(b) & 0xFFFF0000u);
    uint32_t r;
    asm("cvt.rn.bf16x2.f32 %0, %1, %2;" : "=r"(r) : "f"(lb), "f"(la));
    return r;
}
// fp16 RN pack (a -> low half)
__device__ __forceinline__ uint32_t pkh2(float a, float b) {
    uint32_t r;
    asm("cvt.rn.f16x2.f32 %0, %1, %2;" : "=r"(r) : "f"(b), "f"(a));
    return r;
}
// fp16 hi/lo split of a float pair
__device__ __forceinline__ void split_f16(float a, float b, uint32_t& hi, uint32_t& lo) {
    __half ha = __float2half_rn(a);
    __half hb = __float2half_rn(b);
    hi = ((uint32_t)__half_as_ushort(hb) << 16) | __half_as_ushort(ha);
    lo = pkh2(a - __half2float(ha), b - __half2float(hb));
}

// ---------------------------------------------------------------------------
// fp32 -> fp16 hi/lo split (activations)
// ---------------------------------------------------------------------------
__global__ __launch_bounds__(256) void split_x_f16(const float4* __restrict__ src,
                                                   uint32_t* __restrict__ hi,
                                                   uint32_t* __restrict__ lo,
                                                   int n4) {
    int i = blockIdx.x * 256 + threadIdx.x;
    if (i >= n4) return;
    float4 v = src[i];
    uint32_t h0, l0, h1, l1;
    split_f16(v.x, v.y, h0, l0);
    split_f16(v.z, v.w, h1, l1);
    hi[2 * i] = h0; hi[2 * i + 1] = h1;
    lo[2 * i] = l0; lo[2 * i + 1] = l1;
}
// fp32 -> fp16 RN (weights, hi only)
__global__ __launch_bounds__(256) void split_w_f16(const float4* __restrict__ src,
                                                   uint32_t* __restrict__ hi, int n4) {
    int i = blockIdx.x * 256 + threadIdx.x;
    if (i >= n4) return;
    float4 v = src[i];
    hi[2 * i]     = pkh2(v.x, v.y);
    hi[2 * i + 1] = pkh2(v.z, v.w);
}

// ---------------------------------------------------------------------------
// fp16 2-term GEMM: C[M,N] = (Ah+Al)[M,K] @ Wh[N,K]^T, fp32 accumulate.
// BM=128 BN=128 BK=32, 256 thr (8 warps 2x4), warp tile 64x32, 3-stage
// cp.async. OUTBF=1: fused QKV (grid.x=24, widx=bn>>3), bf16 hi/lo head-major.
// ---------------------------------------------------------------------------
constexpr int ROWB = 80;
constexpr int TILEB = 128 * ROWB;            // 10240
constexpr int A_REG = 3 * 2 * TILEB;         // 3 stages x {hi,lo}
constexpr int GEMM_SMEM = A_REG + 3 * TILEB; // + B hi (3 stages) = 92160
constexpr int NKT = DM / 32;

template <int OUTBF>
__global__ __launch_bounds__(256) void gemm_f16(const __half* __restrict__ Ah,
                                                const __half* __restrict__ Al,
                                                const __half* __restrict__ Wh,
                                                float* __restrict__ C,
                                                __nv_bfloat16* __restrict__ QKVhi,
                                                __nv_bfloat16* __restrict__ QKVlo) {
    extern __shared__ char smem[];
    const uint32_t sb = smem_u32(smem);
    const int tid = threadIdx.x;
    const int lane = tid & 31;
    const int wid = tid >> 5;
    const int warpM = wid & 1;
    const int warpN = wid >> 1;
    const int bn = blockIdx.x;
    const int bm = blockIdx.y;
    const int widx = (OUTBF == 1) ? (bn >> 3) : 0;
    const int bnl = (OUTBF == 1) ? (bn & 7) : bn;
    const int rowA0 = bm * 128;
    const int rowB0 = bnl * 128;
    const __half* Bh = Wh + (size_t)widx * DM * DM;

    const int lr0 = tid >> 2;
    const int lc = (tid & 3) * 8;

    auto load_stage = [&](int kt, int buf) {
        const size_t gkoff = (size_t)kt * 32 + lc;
#pragma unroll
        for (int it = 0; it < 2; it++) {
            int r = lr0 + it * 64;
            uint32_t so = (uint32_t)(r * ROWB + (tid & 3) * 16);
            size_t ga = (size_t)(rowA0 + r) * DM + gkoff;
            size_t gb = (size_t)(rowB0 + r) * DM + gkoff;
            uint32_t abase = sb + buf * 2 * TILEB;
            uint32_t bbase = sb + A_REG + buf * TILEB;
            cp16(abase + so,         Ah + ga);
            cp16(abase + TILEB + so, Al + ga);
            cp16(bbase + so,         Bh + gb);
        }
        cp_commit();
    };

    float acc[4][4][4];
#pragma unroll
    for (int i = 0; i < 4; i++)
#pragma unroll
        for (int j = 0; j < 4; j++)
#pragma unroll
            for (int e = 0; e < 4; e++) acc[i][j][e] = 0.f;

    load_stage(0, 0);
    load_stage(1, 1);

    const int a_r = (lane & 15);
    const int a_c8 = (lane >> 4) * 8;
    const int b_r = ((lane >> 4) * 8) + (lane & 7);
    const int b_c8 = ((lane >> 3) & 1) * 8;

    for (int kt = 0; kt < NKT; kt++) {
        const int buf = kt % 3;
        cp_waitg<1>();
        __syncthreads();

        int ktn = kt + 2;
        if (ktn > NKT - 1) ktn = NKT - 1;
        load_stage(ktn, (kt + 2) % 3);

        const uint32_t aHi = sb + buf * 2 * TILEB;
        const uint32_t aLo = aHi + TILEB;
        const uint32_t bHi = sb + A_REG + buf * TILEB;
        const int mrow = warpM * 64 + a_r;
        const int nrow = warpN * 32 + b_r;

#pragma unroll
        for (int ks = 0; ks < 2; ks++) {
            uint32_t ah[4][4], al[4][4], bh[2][4];
            const uint32_t acol = (uint32_t)((ks * 16 + a_c8) * 2);
            const uint32_t bcol = (uint32_t)((ks * 16 + b_c8) * 2);
#pragma unroll
            for (int mt = 0; mt < 4; mt++) {
                uint32_t ro = (uint32_t)((mrow + mt * 16) * ROWB) + acol;
                ldsm4(ah[mt], aHi + ro);
                ldsm4(al[mt], aLo + ro);
            }
#pragma unroll
            for (int np = 0; np < 2; np++) {
                uint32_t ro = (uint32_t)((nrow + np * 16) * ROWB) + bcol;
                ldsm4(bh[np], bHi + ro);
            }
#pragma unroll
            for (int mt = 0; mt < 4; mt++)
#pragma unroll
                for (int np = 0; np < 2; np++)
#pragma unroll
                    for (int ns = 0; ns < 2; ns++) {
                        float* c = acc[mt][np * 2 + ns];
                        mma16816h(c, ah[mt], &bh[np][ns * 2]);
                        mma16816h(c, al[mt], &bh[np][ns * 2]);
                    }
        }
        __syncthreads();
    }

    const int rbase = bm * 128 + warpM * 64 + (lane >> 2);
    const int cbase = bnl * 128 + warpN * 32 + (lane & 3) * 2;
    __nv_bfloat16* Chi = QKVhi + (size_t)widx * M * DM;
    __nv_bfloat16* Clo = QKVlo + (size_t)widx * M * DM;
#pragma unroll
    for (int mt = 0; mt < 4; mt++) {
#pragma unroll
        for (int nt = 0; nt < 4; nt++) {
            int row = rbase + mt * 16;
            int col = cbase + nt * 8;
#pragma unroll
            for (int half = 0; half < 2; half++) {
                int r = row + half * 8;
                float vx = acc[mt][nt][half * 2];
                float vy = acc[mt][nt][half * 2 + 1];
                if (OUTBF == 0) {
                    *(float2*)(C + (size_t)r * DM + col) = make_float2(vx, vy);
                } else {
                    int b_ = r >> 11;
                    int s_ = r & 2047;
                    int h_ = col >> 6;
                    int d_ = col & 63;
                    size_t idx = ((((size_t)b_ * H + h_) * S + s_) << 6) + d_;
                    *(uint32_t*)(Chi + idx) = pk_hi2(vx, vy);
                    *(uint32_t*)(Clo + idx) = pk_lo2(vx, vy);
                }
            }
        }
    }
}

// ---------------------------------------------------------------------------
// Tensor-core causal flash attention, bf16 3-term split (proven 6e-5 path).
// 128 thr (4 warps), 64 queries/CTA, KV tiles of 64, double-buffered cp.async.
// Writes AO as fp16 hi/lo [b, s, h*64+d] for the fp16 O-projection.
// ---------------------------------------------------------------------------
constexpr int AROWB = 144;
constexpr int ATILE = 64 * AROWB;
constexpr int ASTG = 4 * ATILE;
constexpr int ATT_SMEM = 2 * ASTG;

__global__ __launch_bounds__(128) void attn_mma(
    const __nv_bfloat16* __restrict__ QKVh, const __nv_bfloat16* __restrict__ QKVl,
    __half* __restrict__ AOh, __half* __restrict__ AOl) {
    extern __shared__ char smem[];
    const uint32_t sb = smem_u32(smem);
    const int tid = threadIdx.x;
    const int lane = tid & 31;
    const int wid = tid >> 5;
    const int qt = blockIdx.x;
    const int h = blockIdx.y;
    const int b = blockIdx.z;
    const size_t hb = (((size_t)b * H + h) * S) * DH;
    const __nv_bfloat16* Qh = QKVh;
    const __nv_bfloat16* Ql = QKVl;
    const __nv_bfloat16* Kh = QKVh + (size_t)M * DM;
    const __nv_bfloat16* Kl = QKVl + (size_t)M * DM;
    const __nv_bfloat16* Vh = QKVh + (size_t)2 * M * DM;
    const __nv_bfloat16* Vl = QKVl + (size_t)2 * M * DM;

    // Stage Q (64x64 hi/lo) into buffer 0, extract to regs
#pragma unroll
    for (int i = 0; i < 4; i++) {
        int id = tid + i * 128;
        int r = id >> 3, c = id & 7;
        uint32_t so = (uint32_t)(r * AROWB + c * 16);
        size_t g = hb + (size_t)(qt * 64 + r) * DH + c * 8;
        cp16(sb + so, Qh + g);
        cp16(sb + ATILE + so, Ql + g);
    }
    cp_commit();
    cp_waitg<0>();
    __syncthreads();

    uint32_t qh[4][4], ql[4][4];
    {
        int row = wid * 16 + (lane & 15);
#pragma unroll
        for (int ks = 0; ks < 4; ks++) {
            uint32_t off = (uint32_t)(row * AROWB + (ks * 16 + (lane >> 4) * 8) * 2);
            ldsm4(qh[ks], sb + off);
            ldsm4(ql[ks], sb + ATILE + off);
        }
    }
    __syncthreads();

    float ov[8][4];
#pragma unroll
    for (int o = 0; o < 8; o++)
#pragma unroll
        for (int e = 0; e < 4; e++) ov[o][e] = 0.f;
    float m0 = -1e30f, m1 = -1e30f, l0 = 0.f, l1 = 0.f;

    const int nkt = qt + 1;

    auto load_kv = [&](int kt, int bufi) {
        uint32_t base = sb + bufi * ASTG;
#pragma unroll
        for (int i = 0; i < 4; i++) {
            int id = tid + i * 128;
            int r = id >> 3, c = id & 7;
            uint32_t so = (uint32_t)(r * AROWB + c * 16);
            size_t g = hb + (size_t)(kt * 64 + r) * DH + c * 8;
            cp16(base + so,             Kh + g);
            cp16(base + ATILE + so,     Kl + g);
            cp16(base + 2 * ATILE + so, Vh + g);
            cp16(base + 3 * ATILE + so, Vl + g);
        }
        cp_commit();
    };
    load_kv(0, 0);

    for (int kt = 0; kt < nkt; kt++) {
        const int buf = kt & 1;
        if (kt + 1 < nkt) { load_kv(kt + 1, buf ^ 1); cp_waitg<1>(); }
        else              { cp_waitg<0>(); }
        __syncthreads();
        const uint32_t kb = sb + buf * ASTG;

        // S = Qh*Kh + Ql*Kh + Qh*Kl
        float sf[8][4];
#pragma unroll
        for (int o = 0; o < 8; o++)
#pragma unroll
            for (int e = 0; e < 4; e++) sf[o][e] = 0.f;

#pragma unroll
        for (int ks = 0; ks < 4; ks++) {
#pragma unroll
            for (int np = 0; np < 4; np++) {
                uint32_t kh4[4], kl4[4];
                uint32_t ro = (uint32_t)(
                    (np * 16 + (lane >> 4) * 8 + (lane & 7)) * AROWB +
                    (ks * 16 + ((lane >> 3) & 1) * 8) * 2);
                ldsm4(kh4, kb + ro);
                ldsm4(kl4, kb + ATILE + ro);
#pragma unroll
                for (int ns = 0; ns < 2; ns++) {
                    float* c = sf[np * 2 + ns];
                    mma16816(c, qh[ks], &kh4[ns * 2]);
                    mma16816(c, qh[ks], &kl4[ns * 2]);
                    mma16816(c, ql[ks], &kh4[ns * 2]);
                }
            }
        }

        // online softmax (fp32)
        const bool diag = (kt == qt);
        const int r0 = lane >> 2;
        const int q0 = wid * 16 + r0;
        const int q1 = q0 + 8;
        float mx0 = -1e30f, mx1 = -1e30f;
#pragma unroll
        for (int o = 0; o < 8; o++) {
#pragma unroll
            for (int e = 0; e < 2; e++) {
                int keyl = o * 8 + (lane & 3) * 2 + e;
                float v0 = sf[o][e] * 0.125f;
                float v1 = sf[o][2 + e] * 0.125f;
                if (diag && keyl > q0) v0 = -1e30f;
                if (diag && keyl > q1) v1 = -1e30f;
                sf[o][e] = v0;
                sf[o][2 + e] = v1;
                mx0 = fmaxf(mx0, v0);
                mx1 = fmaxf(mx1, v1);
            }
        }
        mx0 = fmaxf(mx0, __shfl_xor_sync(0xffffffffu, mx0, 1));
        mx0 = fmaxf(mx0, __shfl_xor_sync(0xffffffffu, mx0, 2));
        mx1 = fmaxf(mx1, __shfl_xor_sync(0xffffffffu, mx1, 1));
        mx1 = fmaxf(mx1, __shfl_xor_sync(0xffffffffu, mx1, 2));
        const float mn0 = fmaxf(m0, mx0);
        const float mn1 = fmaxf(m1, mx1);
        const float es0 = __expf(m0 - mn0);
        const float es1 = __expf(m1 - mn1);
        m0 = mn0; m1 = mn1;

        float rs0 = 0.f, rs1 = 0.f;
#pragma unroll
        for (int o = 0; o < 8; o++) {
#pragma unroll
            for (int e = 0; e < 2; e++) {
                float p0 = __expf(sf[o][e] - mn0);
                float p1 = __expf(sf[o][2 + e] - mn1);
                sf[o][e] = p0;
                sf[o][2 + e] = p1;
                rs0 += p0;
                rs1 += p1;
            }
        }
        rs0 += __shfl_xor_sync(0xffffffffu, rs0, 1);
        rs0 += __shfl_xor_sync(0xffffffffu, rs0, 2);
        rs1 += __shfl_xor_sync(0xffffffffu, rs1, 1);
        rs1 += __shfl_xor_sync(0xffffffffu, rs1, 2);
        l0 = l0 * es0 + rs0;
        l1 = l1 * es1 + rs1;
#pragma unroll
        for (int o = 0; o < 8; o++) {
            ov[o][0] *= es0; ov[o][1] *= es0;
            ov[o][2] *= es1; ov[o][3] *= es1;
        }

        // O += Ph*Vh + Pl*Vh + Ph*Vl
#pragma unroll
        for (int kp = 0; kp < 4; kp++) {
            uint32_t pah[4], pal[4];
            pah[0] = pk_hi2(sf[2 * kp][0], sf[2 * kp][1]);
            pah[1] = pk_hi2(sf[2 * kp][2], sf[2 * kp][3]);
            pah[2] = pk_hi2(sf[2 * kp + 1][0], sf[2 * kp + 1][1]);
            pah[3] = pk_hi2(sf[2 * kp + 1][2], sf[2 * kp + 1][3]);
            pal[0] = pk_lo2(sf[2 * kp][0], sf[2 * kp][1]);
            pal[1] = pk_lo2(sf[2 * kp][2], sf[2 * kp][3]);
            pal[2] = pk_lo2(sf[2 * kp + 1][0], sf[2 * kp + 1][1]);
            pal[3] = pk_lo2(sf[2 * kp + 1][2], sf[2 * kp + 1][3]);
#pragma unroll
            for (int dp = 0; dp < 4; dp++) {
                uint32_t bvh[4], bvl[4];
                uint32_t vo = (uint32_t)(
                    (kp * 16 + (lane & 15)) * AROWB +
                    (dp * 16 + (lane >> 4) * 8) * 2);
                ldsm4t(bvh, kb + 2 * ATILE + vo);
                ldsm4t(bvl, kb + 3 * ATILE + vo);
#pragma unroll
                for (int ns = 0; ns < 2; ns++) {
                    float* o_ = ov[dp * 2 + ns];
                    mma16816(o_, pah, &bvh[ns * 2]);
                    mma16816(o_, pal, &bvh[ns * 2]);
                    mma16816(o_, pah, &bvl[ns * 2]);
                }
            }
        }
        __syncthreads();
    }

    // epilogue: normalize, split to fp16 hi/lo, write [b, s, h*64 + d]
    const float inv0 = 1.f / l0;
    const float inv1 = 1.f / l1;
    const int s0 = qt * 64 + wid * 16 + (lane >> 2);
    const size_t row0 = ((size_t)b * S + s0) * DM + h * DH;
    const size_t row1 = row0 + (size_t)8 * DM;
#pragma unroll
    for (int o = 0; o < 8; o++) {
        int d = o * 8 + (lane & 3) * 2;
        uint32_t hi0, lo0, hi1, lo1;
        split_f16(ov[o][0] * inv0, ov[o][1] * inv0, hi0, lo0);
        split_f16(ov[o][2] * inv1, ov[o][3] * inv1, hi1, lo1);
        *(uint32_t*)(AOh + row0 + d) = hi0;
        *(uint32_t*)(AOl + row0 + d) = lo0;
        *(uint32_t*)(AOh + row1 + d) = hi1;
        *(uint32_t*)(AOl + row1 + d) = lo1;
    }
}

// ---------------------------------------------------------------------------
extern "C" void kernel_launch(void* const* d_in, const int* in_sizes, int n_in,
                              void* d_out, int out_size) {
    const float* w[4] = {nullptr, nullptr, nullptr, nullptr};
    const float* x = nullptr;
    int wn = 0;
    for (int i = 0; i < n_in; i++) {
        if (in_sizes[i] == DM * DM && wn < 4) {
            w[wn++] = (const float*)d_in[i];
        } else if (in_sizes[i] == B * S * DM) {
            x = (const float*)d_in[i];
        }
    }

    __half *xhi, *xlo, *whi, *aohi, *aolo;
    __nv_bfloat16 *qkvhi, *qkvlo;
    cudaGetSymbolAddress((void**)&xhi, g_xhi);
    cudaGetSymbolAddress((void**)&xlo, g_xlo);
    cudaGetSymbolAddress((void**)&whi, g_whi);
    cudaGetSymbolAddress((void**)&qkvhi, g_qkvhi);
    cudaGetSymbolAddress((void**)&qkvlo, g_qkvlo);
    cudaGetSymbolAddress((void**)&aohi, g_aohi);
    cudaGetSymbolAddress((void**)&aolo, g_aolo);

    cudaFuncSetAttribute(gemm_f16<0>, cudaFuncAttributeMaxDynamicSharedMemorySize, GEMM_SMEM);
    cudaFuncSetAttribute(gemm_f16<1>, cudaFuncAttributeMaxDynamicSharedMemorySize, GEMM_SMEM);
    cudaFuncSetAttribute(attn_mma, cudaFuncAttributeMaxDynamicSharedMemorySize, ATT_SMEM);

    const int xn4 = (M * DM) / 4;
    const int wn4 = (DM * DM) / 4;
    split_x_f16<<<(xn4 + 255) / 256, 256>>>((const float4*)x,
                                            (uint32_t*)xhi, (uint32_t*)xlo, xn4);
    for (int i = 0; i < 4; i++) {
        split_w_f16<<<(wn4 + 255) / 256, 256>>>((const float4*)w[i],
                                                (uint32_t*)(whi + (size_t)i * DM * DM), wn4);
    }

    // Fused QKV projection: one launch, 1536 CTAs
    dim3 qkvgrid(3 * DM / 128, M / 128);  // (24, 64)
    gemm_f16<1><<<qkvgrid, 256, GEMM_SMEM>>>(xhi, xlo, whi, nullptr, qkvhi, qkvlo);

    dim3 agrid(S / 64, H, B);  // (32, 16, 4)
    attn_mma<<<agrid, 128, ATT_SMEM>>>(qkvhi, qkvlo, aohi, aolo);

    dim3 ogrid(DM / 128, M / 128);  // (8, 64)
    gemm_f16<0><<<ogrid, 256, GEMM_SMEM>>>(aohi, aolo, whi + (size_t)3 * DM * DM,
                                           (float*)d_out, nullptr, nullptr);
}